// round 3
// baseline (speedup 1.0000x reference)
#include <cuda_runtime.h>
#include <cuda_bf16.h>
#include <math.h>

// Problem constants (fixed shapes from reference)
#define N_TOK 2048
#define HDIM  2048
#define IDIM  1408
#define NEXP  64
#define NGRP  8
#define GSZ   8
#define TOPK  8

// ---------------------------------------------------------------------------
// Scratch (device globals; no runtime allocation allowed)
// ---------------------------------------------------------------------------
__device__ float g_soft[(size_t)N_TOK * NGRP * GSZ];     // softmax over group slots
__device__ float g_scalar[(size_t)N_TOK * NGRP];         // per-(token,group) weight
__device__ float g_Pg[(size_t)NGRP * IDIM * GSZ];        // Wg @ mask_up  (I x 8 per group)
__device__ float g_Pu[(size_t)NGRP * IDIM * GSZ];        // Wu @ mask_up
__device__ float g_act[(size_t)NGRP * N_TOK * IDIM];     // scalar * silu(g)*u  (92 MB)

// ---------------------------------------------------------------------------
// Kernel R: routing. One block per token.
//   logits = x . gate_w^T ; softmax ; top-8 ; per-group scalar + masked softmax
//   inv_map may be serialized as int32 (JAX x64 disabled) or int64 — detect.
// ---------------------------------------------------------------------------
__global__ __launch_bounds__(256) void moe_route(
    const float* __restrict__ x, const float* __restrict__ gate_w,
    const void* __restrict__ inv_map_raw)
{
    __shared__ float xs[HDIM];
    __shared__ float sc[NEXP];
    __shared__ float we[NEXP];

    const int n   = blockIdx.x;
    const int tid = threadIdx.x;

    const float4* xr4 = (const float4*)(x + (size_t)n * HDIM);
    for (int i = tid; i < HDIM / 4; i += 256)
        ((float4*)xs)[i] = xr4[i];
    __syncthreads();

    const int warp = tid >> 5, lane = tid & 31;
    // warp w owns experts [8w, 8w+8)
    float acc[8];
#pragma unroll
    for (int j = 0; j < 8; j++) acc[j] = 0.f;
    const float* gw = gate_w + (size_t)(warp * 8) * HDIM;
    for (int h = lane; h < HDIM; h += 32) {
        float xv = xs[h];
#pragma unroll
        for (int j = 0; j < 8; j++)
            acc[j] += xv * gw[(size_t)j * HDIM + h];
    }
#pragma unroll
    for (int j = 0; j < 8; j++) {
        float v = acc[j];
#pragma unroll
        for (int o = 16; o > 0; o >>= 1) v += __shfl_down_sync(0xffffffffu, v, o);
        if (lane == 0) sc[warp * 8 + j] = v;
    }
    __syncthreads();

    if (tid == 0) {
        float mx = -1e30f;
        for (int e = 0; e < NEXP; e++) mx = fmaxf(mx, sc[e]);
        float sum = 0.f;
        for (int e = 0; e < NEXP; e++) { float v = expf(sc[e] - mx); sc[e] = v; sum += v; }
        float inv = 1.f / sum;
        for (int e = 0; e < NEXP; e++) { sc[e] *= inv; we[e] = 0.f; }
        // top-8 (first-index wins on ties, matching lax.top_k)
        for (int k = 0; k < TOPK; k++) {
            int bi = 0; float bv = sc[0];
            for (int e = 1; e < NEXP; e++) if (sc[e] > bv) { bv = sc[e]; bi = e; }
            we[bi] = bv; sc[bi] = -1.f;
        }
    }
    __syncthreads();

    if (tid < NGRP) {
        const int g = tid;
        // dtype detection: inv_map is arange(64); as int64 its int32-view has
        // word[1]==0, as int32 word[1]==1.
        const int* im32 = (const int*)inv_map_raw;
        const bool is64 = (im32[1] == 0);
        const long long* im64 = (const long long*)inv_map_raw;

        float f[GSZ]; float ss = 0.f;
#pragma unroll
        for (int s = 0; s < GSZ; s++) {
            const int slot = g * GSZ + s;
            const int e = is64 ? (int)im64[slot] : im32[slot];
            f[s] = we[e];
            ss += f[s];
        }
        g_scalar[(size_t)n * NGRP + g] = ss;
        float mx = -1e30f;
#pragma unroll
        for (int s = 0; s < GSZ; s++) {
            float v = (f[s] == 0.f) ? -1e9f : f[s];
            f[s] = v; mx = fmaxf(mx, v);
        }
        float es = 0.f;
#pragma unroll
        for (int s = 0; s < GSZ; s++) { float v = expf(f[s] - mx); f[s] = v; es += v; }
        float inv = 1.f / es;
#pragma unroll
        for (int s = 0; s < GSZ; s++)
            g_soft[((size_t)n * NGRP + g) * GSZ + s] = f[s] * inv;
    }
}

// ---------------------------------------------------------------------------
// Kernel P: P_g[g,i,s] = sum_h Wg[g,i,h] * M[g,h,s]  (and same for Wu).
// One warp per (g,i).
// ---------------------------------------------------------------------------
__global__ __launch_bounds__(256) void moe_pproj(
    const float* __restrict__ Wg, const float* __restrict__ Wu,
    const float* __restrict__ M)
{
    const int wid  = blockIdx.x * 8 + (threadIdx.x >> 5);
    const int lane = threadIdx.x & 31;
    const int g = wid / IDIM, i = wid % IDIM;

    const float* wgr = Wg + ((size_t)g * IDIM + i) * HDIM;
    const float* wur = Wu + ((size_t)g * IDIM + i) * HDIM;
    const float* mg  = M + (size_t)g * HDIM * GSZ;

    float ag[8], au[8];
#pragma unroll
    for (int s = 0; s < 8; s++) { ag[s] = 0.f; au[s] = 0.f; }

    for (int h = lane; h < HDIM; h += 32) {
        float wgv = wgr[h], wuv = wur[h];
        const float4* mr = (const float4*)(mg + (size_t)h * GSZ);
        float4 m0 = mr[0], m1 = mr[1];
        ag[0] += wgv * m0.x; ag[1] += wgv * m0.y; ag[2] += wgv * m0.z; ag[3] += wgv * m0.w;
        ag[4] += wgv * m1.x; ag[5] += wgv * m1.y; ag[6] += wgv * m1.z; ag[7] += wgv * m1.w;
        au[0] += wuv * m0.x; au[1] += wuv * m0.y; au[2] += wuv * m0.z; au[3] += wuv * m0.w;
        au[4] += wuv * m1.x; au[5] += wuv * m1.y; au[6] += wuv * m1.z; au[7] += wuv * m1.w;
    }
#pragma unroll
    for (int s = 0; s < 8; s++) {
#pragma unroll
        for (int o = 16; o > 0; o >>= 1) {
            ag[s] += __shfl_down_sync(0xffffffffu, ag[s], o);
            au[s] += __shfl_down_sync(0xffffffffu, au[s], o);
        }
    }
    if (lane == 0) {
        float* pg = &g_Pg[((size_t)g * IDIM + i) * GSZ];
        float* pu = &g_Pu[((size_t)g * IDIM + i) * GSZ];
#pragma unroll
        for (int s = 0; s < 8; s++) { pg[s] = ag[s]; pu[s] = au[s]; }
    }
}

// ---------------------------------------------------------------------------
// Kernel G1: fused gate+up base GEMM + rank-8 correction + silu*u*scalar.
//   tile: 128 tokens x 64 i per block; 256 threads; thread tile 8x4, dual acc.
//   act[g,n,i] = scalar[n,g] * silu(gbase+gc) * (ubase+uc)
// ---------------------------------------------------------------------------
__global__ __launch_bounds__(256) void moe_g1(
    const float* __restrict__ x, const float* __restrict__ Wg,
    const float* __restrict__ Wu)
{
    __shared__ float Xs[16][132];
    __shared__ float Gs[16][68];
    __shared__ float Us[16][68];

    const int g  = blockIdx.z;
    const int n0 = blockIdx.y * 128;
    const int i0 = blockIdx.x * 64;
    const int tid = threadIdx.x;
    const int tx = tid & 15, ty = tid >> 4;

    const float* xp = x  + (size_t)n0 * HDIM;
    const float* gp = Wg + ((size_t)g * IDIM + i0) * HDIM;
    const float* up = Wu + ((size_t)g * IDIM + i0) * HDIM;

    float ag[8][4], au[8][4];
#pragma unroll
    for (int m = 0; m < 8; m++)
#pragma unroll
        for (int nn = 0; nn < 4; nn++) { ag[m][nn] = 0.f; au[m][nn] = 0.f; }

    const int wr = tid >> 2;
    const int wc = (tid & 3) << 2;

    for (int k0 = 0; k0 < HDIM; k0 += 16) {
#pragma unroll
        for (int l = 0; l < 2; l++) {
            int id = tid + l * 256;
            int r = id >> 2, c = (id & 3) << 2;
            float4 v = *(const float4*)(xp + (size_t)r * HDIM + k0 + c);
            Xs[c][r] = v.x; Xs[c + 1][r] = v.y; Xs[c + 2][r] = v.z; Xs[c + 3][r] = v.w;
        }
        {
            float4 v = *(const float4*)(gp + (size_t)wr * HDIM + k0 + wc);
            Gs[wc][wr] = v.x; Gs[wc + 1][wr] = v.y; Gs[wc + 2][wr] = v.z; Gs[wc + 3][wr] = v.w;
            float4 u = *(const float4*)(up + (size_t)wr * HDIM + k0 + wc);
            Us[wc][wr] = u.x; Us[wc + 1][wr] = u.y; Us[wc + 2][wr] = u.z; Us[wc + 3][wr] = u.w;
        }
        __syncthreads();
#pragma unroll
        for (int k = 0; k < 16; k++) {
            float a[8], bg[4], bu[4];
#pragma unroll
            for (int m = 0; m < 8; m++) a[m] = Xs[k][ty * 8 + m];
#pragma unroll
            for (int nn = 0; nn < 4; nn++) { bg[nn] = Gs[k][tx * 4 + nn]; bu[nn] = Us[k][tx * 4 + nn]; }
#pragma unroll
            for (int m = 0; m < 8; m++)
#pragma unroll
                for (int nn = 0; nn < 4; nn++) {
                    ag[m][nn] += a[m] * bg[nn];
                    au[m][nn] += a[m] * bu[nn];
                }
        }
        __syncthreads();
    }

    // epilogue: rank-8 correction, silu * up, fold scalar
    const int nbase = n0 + ty * 8;
    const int ibase = i0 + tx * 4;
#pragma unroll
    for (int m = 0; m < 8; m++) {
        const int n = nbase + m;
        const float* sft = &g_soft[((size_t)n * NGRP + g) * GSZ];
        float s0 = sft[0], s1 = sft[1], s2 = sft[2], s3 = sft[3];
        float s4 = sft[4], s5 = sft[5], s6 = sft[6], s7 = sft[7];
        const float scl = g_scalar[(size_t)n * NGRP + g];
#pragma unroll
        for (int nn = 0; nn < 4; nn++) {
            const int i = ibase + nn;
            const float* pg = &g_Pg[((size_t)g * IDIM + i) * GSZ];
            const float* pu = &g_Pu[((size_t)g * IDIM + i) * GSZ];
            float gv = ag[m][nn], uv = au[m][nn];
            gv += s0 * pg[0] + s1 * pg[1] + s2 * pg[2] + s3 * pg[3]
                + s4 * pg[4] + s5 * pg[5] + s6 * pg[6] + s7 * pg[7];
            uv += s0 * pu[0] + s1 * pu[1] + s2 * pu[2] + s3 * pu[3]
                + s4 * pu[4] + s5 * pu[5] + s6 * pu[6] + s7 * pu[7];
            float sig = 1.f / (1.f + expf(-gv));
            g_act[((size_t)g * N_TOK + n) * IDIM + i] = scl * (gv * sig * uv);
        }
    }
}

// ---------------------------------------------------------------------------
// Kernel G2: y[n,h] = sum_g sum_i act[g,n,i] * Wd[g,h,i]
//   tile 128x128, 256 threads, 8x8 per thread, g folded into the K loop.
// ---------------------------------------------------------------------------
__global__ __launch_bounds__(256) void moe_g2(
    const float* __restrict__ Wd, float* __restrict__ y)
{
    __shared__ float As[16][132];
    __shared__ float Bs[16][132];

    const int n0 = blockIdx.y * 128;
    const int h0 = blockIdx.x * 128;
    const int tid = threadIdx.x;
    const int tx = tid & 15, ty = tid >> 4;

    float acc[8][8];
#pragma unroll
    for (int m = 0; m < 8; m++)
#pragma unroll
        for (int nn = 0; nn < 8; nn++) acc[m][nn] = 0.f;

    for (int g = 0; g < NGRP; g++) {
        const float* ap = g_act + ((size_t)g * N_TOK + n0) * IDIM;
        const float* bp = Wd + ((size_t)g * HDIM + h0) * IDIM;
        for (int k0 = 0; k0 < IDIM; k0 += 16) {
#pragma unroll
            for (int l = 0; l < 2; l++) {
                int id = tid + l * 256;
                int r = id >> 2, c = (id & 3) << 2;
                float4 va = *(const float4*)(ap + (size_t)r * IDIM + k0 + c);
                As[c][r] = va.x; As[c + 1][r] = va.y; As[c + 2][r] = va.z; As[c + 3][r] = va.w;
                float4 vb = *(const float4*)(bp + (size_t)r * IDIM + k0 + c);
                Bs[c][r] = vb.x; Bs[c + 1][r] = vb.y; Bs[c + 2][r] = vb.z; Bs[c + 3][r] = vb.w;
            }
            __syncthreads();
#pragma unroll
            for (int k = 0; k < 16; k++) {
                float a[8], b[8];
#pragma unroll
                for (int m = 0; m < 8; m++) a[m] = As[k][ty * 8 + m];
#pragma unroll
                for (int nn = 0; nn < 8; nn++) b[nn] = Bs[k][tx * 8 + nn];
#pragma unroll
                for (int m = 0; m < 8; m++)
#pragma unroll
                    for (int nn = 0; nn < 8; nn++) acc[m][nn] += a[m] * b[nn];
            }
            __syncthreads();
        }
    }
#pragma unroll
    for (int m = 0; m < 8; m++)
#pragma unroll
        for (int nn = 0; nn < 8; nn++)
            y[(size_t)(n0 + ty * 8 + m) * HDIM + h0 + tx * 8 + nn] = acc[m][nn];
}

// ---------------------------------------------------------------------------
// Launch
// ---------------------------------------------------------------------------
extern "C" void kernel_launch(void* const* d_in, const int* in_sizes, int n_in,
                              void* d_out, int out_size)
{
    const float* x      = (const float*)d_in[0];      // (1,2048,2048)
    const float* gate_w = (const float*)d_in[1];      // (64,2048)
    const float* mask_w = (const float*)d_in[2];      // (8,2048,8)
    const float* Wg     = (const float*)d_in[3];      // (8,1408,2048)
    const float* Wu     = (const float*)d_in[4];      // (8,1408,2048)
    const float* Wd     = (const float*)d_in[5];      // (8,2048,1408)
    const void*  invmap = (const void*)d_in[6];       // (8,8) int32 or int64
    float* y = (float*)d_out;

    (void)in_sizes; (void)n_in; (void)out_size;

    // routing (independent of P)
    moe_route<<<N_TOK, 256>>>(x, gate_w, invmap);

    // rank-8 projections P_g = W @ mask_up
    moe_pproj<<<(NGRP * IDIM) / 8, 256>>>(Wg, Wu, mask_w);

    // fused gate/up GEMM + epilogue -> act
    dim3 g1grid(IDIM / 64, N_TOK / 128, NGRP);
    moe_g1<<<g1grid, 256>>>(x, Wg, Wu);

    // down GEMM accumulated over groups -> y
    dim3 g2grid(HDIM / 128, N_TOK / 128);
    moe_g2<<<g2grid, 256>>>(Wd, y);
}

// round 5
// speedup vs baseline: 2.3908x; 2.3908x over previous
#include <cuda_runtime.h>
#include <cuda_bf16.h>
#include <math.h>
#include <stdint.h>

// Problem constants
#define N_TOK 2048
#define HDIM  2048
#define IDIM  1408
#define NEXP  64
#define NGRP  8
#define GSZ   8
#define TOPK  8

// GEMM tiling
#define KC      32                 // bf16 K elems per stage
#define ROWB    80                 // smem row stride bytes (64B data + 16B pad)
#define TILE_SZ (128*ROWB)         // 10240 B
#define STAGE_SZ (4*TILE_SZ)       // Ah,Al,Bh,Bl = 40960 B
#define SMEM_TOTAL (2*STAGE_SZ)    // 81920 B
#define NC1 (HDIM/KC)              // 64
#define KCI (IDIM/KC)              // 44
#define NC2 (NGRP*KCI)             // 352

// ---------------------------------------------------------------------------
// Device global scratch
// ---------------------------------------------------------------------------
__device__ float g_soft[(size_t)N_TOK * NGRP * GSZ];
__device__ float g_scalar[(size_t)N_TOK * NGRP];
__device__ float g_Pg[(size_t)NGRP * IDIM * GSZ];
__device__ float g_Pu[(size_t)NGRP * IDIM * GSZ];

__device__ __nv_bfloat16 g_xh[(size_t)N_TOK * HDIM];
__device__ __nv_bfloat16 g_xl[(size_t)N_TOK * HDIM];
__device__ __nv_bfloat16 g_wgh[(size_t)NGRP * IDIM * HDIM];
__device__ __nv_bfloat16 g_wgl[(size_t)NGRP * IDIM * HDIM];
__device__ __nv_bfloat16 g_wuh[(size_t)NGRP * IDIM * HDIM];
__device__ __nv_bfloat16 g_wul[(size_t)NGRP * IDIM * HDIM];
__device__ __nv_bfloat16 g_wdh[(size_t)NGRP * HDIM * IDIM];
__device__ __nv_bfloat16 g_wdl[(size_t)NGRP * HDIM * IDIM];
__device__ __nv_bfloat16 g_acth[(size_t)NGRP * N_TOK * IDIM];
__device__ __nv_bfloat16 g_actl[(size_t)NGRP * N_TOK * IDIM];

// ---------------------------------------------------------------------------
// PTX helpers (sm_80-portable only; NO 'a'-gated features)
// ---------------------------------------------------------------------------
__device__ __forceinline__ uint32_t s2u(const void* p) {
    uint32_t a;
    asm("{ .reg .u64 t; cvta.to.shared.u64 t, %1; cvt.u32.u64 %0, t; }"
        : "=r"(a) : "l"(p));
    return a;
}
__device__ __forceinline__ void cpasync16(uint32_t s, const void* g) {
    asm volatile("cp.async.cg.shared.global [%0], [%1], 16;"
                 :: "r"(s), "l"(g) : "memory");
}
#define CP_COMMIT() asm volatile("cp.async.commit_group;" ::: "memory")
#define CP_WAIT(n)  asm volatile("cp.async.wait_group %0;" :: "n"(n) : "memory")

__device__ __forceinline__ void ldsm4(uint32_t* r, uint32_t addr) {
    asm volatile("ldmatrix.sync.aligned.m8n8.x4.shared.b16 {%0,%1,%2,%3}, [%4];"
                 : "=r"(r[0]), "=r"(r[1]), "=r"(r[2]), "=r"(r[3]) : "r"(addr));
}
__device__ __forceinline__ void mma16816(float* d, const uint32_t* a,
                                         uint32_t b0, uint32_t b1) {
    asm volatile(
        "mma.sync.aligned.m16n8k16.row.col.f32.bf16.bf16.f32 "
        "{%0,%1,%2,%3}, {%4,%5,%6,%7}, {%8,%9}, {%0,%1,%2,%3};"
        : "+f"(d[0]), "+f"(d[1]), "+f"(d[2]), "+f"(d[3])
        : "r"(a[0]), "r"(a[1]), "r"(a[2]), "r"(a[3]), "r"(b0), "r"(b1));
}

// ---------------------------------------------------------------------------
// Prep: fp32 -> bf16 hi/lo split
// ---------------------------------------------------------------------------
__global__ __launch_bounds__(256) void split_bf16(
    const float4* __restrict__ src, uint2* __restrict__ hi, uint2* __restrict__ lo,
    int n4)
{
    for (int i = blockIdx.x * 256 + threadIdx.x; i < n4; i += gridDim.x * 256) {
        float4 v = src[i];
        __nv_bfloat16 h0 = __float2bfloat16(v.x), h1 = __float2bfloat16(v.y);
        __nv_bfloat16 h2 = __float2bfloat16(v.z), h3 = __float2bfloat16(v.w);
        __nv_bfloat16 l0 = __float2bfloat16(v.x - __bfloat162float(h0));
        __nv_bfloat16 l1 = __float2bfloat16(v.y - __bfloat162float(h1));
        __nv_bfloat16 l2 = __float2bfloat16(v.z - __bfloat162float(h2));
        __nv_bfloat16 l3 = __float2bfloat16(v.w - __bfloat162float(h3));
        uint2 H, L;
        H.x = ((uint32_t)__bfloat16_as_ushort(h1) << 16) | __bfloat16_as_ushort(h0);
        H.y = ((uint32_t)__bfloat16_as_ushort(h3) << 16) | __bfloat16_as_ushort(h2);
        L.x = ((uint32_t)__bfloat16_as_ushort(l1) << 16) | __bfloat16_as_ushort(l0);
        L.y = ((uint32_t)__bfloat16_as_ushort(l3) << 16) | __bfloat16_as_ushort(l2);
        hi[i] = H; lo[i] = L;
    }
}

// ---------------------------------------------------------------------------
// Routing
// ---------------------------------------------------------------------------
__global__ __launch_bounds__(256) void moe_route(
    const float* __restrict__ x, const float* __restrict__ gate_w,
    const void* __restrict__ inv_map_raw)
{
    __shared__ float xs[HDIM];
    __shared__ float sc[NEXP];
    __shared__ float we[NEXP];

    const int n = blockIdx.x, tid = threadIdx.x;
    const float4* xr4 = (const float4*)(x + (size_t)n * HDIM);
    for (int i = tid; i < HDIM / 4; i += 256) ((float4*)xs)[i] = xr4[i];
    __syncthreads();

    const int warp = tid >> 5, lane = tid & 31;
    float acc[8];
#pragma unroll
    for (int j = 0; j < 8; j++) acc[j] = 0.f;
    const float* gw = gate_w + (size_t)(warp * 8) * HDIM;
    for (int h = lane; h < HDIM; h += 32) {
        float xv = xs[h];
#pragma unroll
        for (int j = 0; j < 8; j++) acc[j] += xv * gw[(size_t)j * HDIM + h];
    }
#pragma unroll
    for (int j = 0; j < 8; j++) {
        float v = acc[j];
#pragma unroll
        for (int o = 16; o > 0; o >>= 1) v += __shfl_down_sync(0xffffffffu, v, o);
        if (lane == 0) sc[warp * 8 + j] = v;
    }
    __syncthreads();

    if (tid == 0) {
        float mx = -1e30f;
        for (int e = 0; e < NEXP; e++) mx = fmaxf(mx, sc[e]);
        float sum = 0.f;
        for (int e = 0; e < NEXP; e++) { float v = expf(sc[e] - mx); sc[e] = v; sum += v; }
        float inv = 1.f / sum;
        for (int e = 0; e < NEXP; e++) { sc[e] *= inv; we[e] = 0.f; }
        for (int k = 0; k < TOPK; k++) {
            int bi = 0; float bv = sc[0];
            for (int e = 1; e < NEXP; e++) if (sc[e] > bv) { bv = sc[e]; bi = e; }
            we[bi] = bv; sc[bi] = -1.f;
        }
    }
    __syncthreads();

    if (tid < NGRP) {
        const int g = tid;
        const int* im32 = (const int*)inv_map_raw;
        const bool is64 = (im32[1] == 0);
        const long long* im64 = (const long long*)inv_map_raw;
        float f[GSZ]; float ss = 0.f;
#pragma unroll
        for (int s = 0; s < GSZ; s++) {
            const int slot = g * GSZ + s;
            const int e = is64 ? (int)im64[slot] : im32[slot];
            f[s] = we[e]; ss += f[s];
        }
        g_scalar[(size_t)n * NGRP + g] = ss;
        float mx = -1e30f;
#pragma unroll
        for (int s = 0; s < GSZ; s++) {
            float v = (f[s] == 0.f) ? -1e9f : f[s];
            f[s] = v; mx = fmaxf(mx, v);
        }
        float es = 0.f;
#pragma unroll
        for (int s = 0; s < GSZ; s++) { float v = expf(f[s] - mx); f[s] = v; es += v; }
        float inv = 1.f / es;
#pragma unroll
        for (int s = 0; s < GSZ; s++)
            g_soft[((size_t)n * NGRP + g) * GSZ + s] = f[s] * inv;
    }
}

// ---------------------------------------------------------------------------
// P projections (fp32 exact)
// ---------------------------------------------------------------------------
__global__ __launch_bounds__(256) void moe_pproj(
    const float* __restrict__ Wg, const float* __restrict__ Wu,
    const float* __restrict__ M)
{
    const int wid = blockIdx.x * 8 + (threadIdx.x >> 5);
    const int lane = threadIdx.x & 31;
    const int g = wid / IDIM, i = wid % IDIM;

    const float* wgr = Wg + ((size_t)g * IDIM + i) * HDIM;
    const float* wur = Wu + ((size_t)g * IDIM + i) * HDIM;
    const float* mg = M + (size_t)g * HDIM * GSZ;

    float ag[8], au[8];
#pragma unroll
    for (int s = 0; s < 8; s++) { ag[s] = 0.f; au[s] = 0.f; }
    for (int h = lane; h < HDIM; h += 32) {
        float wgv = wgr[h], wuv = wur[h];
        const float4* mr = (const float4*)(mg + (size_t)h * GSZ);
        float4 m0 = mr[0], m1 = mr[1];
        ag[0] += wgv * m0.x; ag[1] += wgv * m0.y; ag[2] += wgv * m0.z; ag[3] += wgv * m0.w;
        ag[4] += wgv * m1.x; ag[5] += wgv * m1.y; ag[6] += wgv * m1.z; ag[7] += wgv * m1.w;
        au[0] += wuv * m0.x; au[1] += wuv * m0.y; au[2] += wuv * m0.z; au[3] += wuv * m0.w;
        au[4] += wuv * m1.x; au[5] += wuv * m1.y; au[6] += wuv * m1.z; au[7] += wuv * m1.w;
    }
#pragma unroll
    for (int s = 0; s < 8; s++) {
#pragma unroll
        for (int o = 16; o > 0; o >>= 1) {
            ag[s] += __shfl_down_sync(0xffffffffu, ag[s], o);
            au[s] += __shfl_down_sync(0xffffffffu, au[s], o);
        }
    }
    if (lane == 0) {
        float* pg = &g_Pg[((size_t)g * IDIM + i) * GSZ];
        float* pu = &g_Pu[((size_t)g * IDIM + i) * GSZ];
#pragma unroll
        for (int s = 0; s < 8; s++) { pg[s] = ag[s]; pu[s] = au[s]; }
    }
}

// ---------------------------------------------------------------------------
// Shared warp-MMA compute step: one Kc=32 stage, split-bf16 3-pass.
//   smem stage layout: [Ah | Al | Bh | Bl], each 128 rows x 64B (stride 80B).
// ---------------------------------------------------------------------------
__device__ __forceinline__ void mma_stage(uint32_t sbuf, int wm, int wn, int lane,
                                          float acc[2][8][4]) {
    const uint32_t lmoff = (uint32_t)((lane & 15) * ROWB + (lane >> 4) * 16);
#pragma unroll
    for (int s = 0; s < 2; s++) {
        const uint32_t base = sbuf + lmoff + s * 32;
        uint32_t ah[2][4], bx[4][4];
        // A hi
        ldsm4(ah[0], base + (wm * 32 + 0) * ROWB);
        ldsm4(ah[1], base + (wm * 32 + 16) * ROWB);
        // B hi
#pragma unroll
        for (int bt = 0; bt < 4; bt++)
            ldsm4(bx[bt], base + 2 * TILE_SZ + (wn * 64 + bt * 16) * ROWB);
        // pass 1: Ah x Bh
#pragma unroll
        for (int mt = 0; mt < 2; mt++)
#pragma unroll
            for (int nt = 0; nt < 8; nt++)
                mma16816(acc[mt][nt], ah[mt],
                         bx[nt >> 1][nt & 1], bx[nt >> 1][2 + (nt & 1)]);
        // pass 2: Al x Bh
        {
            uint32_t al[2][4];
            ldsm4(al[0], base + TILE_SZ + (wm * 32 + 0) * ROWB);
            ldsm4(al[1], base + TILE_SZ + (wm * 32 + 16) * ROWB);
#pragma unroll
            for (int mt = 0; mt < 2; mt++)
#pragma unroll
                for (int nt = 0; nt < 8; nt++)
                    mma16816(acc[mt][nt], al[mt],
                             bx[nt >> 1][nt & 1], bx[nt >> 1][2 + (nt & 1)]);
        }
        // pass 3: Ah x Bl (reuse bx regs)
#pragma unroll
        for (int bt = 0; bt < 4; bt++)
            ldsm4(bx[bt], base + 3 * TILE_SZ + (wn * 64 + bt * 16) * ROWB);
#pragma unroll
        for (int mt = 0; mt < 2; mt++)
#pragma unroll
            for (int nt = 0; nt < 8; nt++)
                mma16816(acc[mt][nt], ah[mt],
                         bx[nt >> 1][nt & 1], bx[nt >> 1][2 + (nt & 1)]);
    }
}

// ---------------------------------------------------------------------------
// G1: act[g, n0..+128, i0..+64] via warp-MMA split-bf16; fused epilogue.
//   C cols: [wn*64 + 0..31] = gate(i0+wn*32+..), [wn*64+32..63] = up(same i)
// ---------------------------------------------------------------------------
__global__ __launch_bounds__(256, 1) void moe_g1_mma()
{
    extern __shared__ char smem[];
    const uint32_t sb = s2u(smem);
    const int tid = threadIdx.x, lane = tid & 31;
    const int wm = (tid >> 5) & 3, wn = tid >> 7;
    const int g = blockIdx.z, i0 = blockIdx.y * 64, n0 = blockIdx.x * 128;

    // per-thread loader slots: 8 x 16B
    const __nv_bfloat16* srcs[8];
    uint32_t dsts[8];
#pragma unroll
    for (int i = 0; i < 8; i++) {
        const int id = tid + i * 256;
        const int tile = id >> 9, rr = (id >> 2) & 127, cc = id & 3;
        const __nv_bfloat16* p;
        if (tile == 0)      p = g_xh + (size_t)(n0 + rr) * HDIM;
        else if (tile == 1) p = g_xl + (size_t)(n0 + rr) * HDIM;
        else {
            const int wnr = rr >> 6, within = rr & 63;
            const int irow = i0 + wnr * 32 + (within & 31);
            const __nv_bfloat16* base =
                (tile == 2) ? ((within < 32) ? g_wgh : g_wuh)
                            : ((within < 32) ? g_wgl : g_wul);
            p = base + ((size_t)g * IDIM + irow) * HDIM;
        }
        srcs[i] = p + cc * 8;
        dsts[i] = sb + tile * TILE_SZ + rr * ROWB + cc * 16;
    }

    float acc[2][8][4];
#pragma unroll
    for (int mt = 0; mt < 2; mt++)
#pragma unroll
        for (int nt = 0; nt < 8; nt++)
#pragma unroll
            for (int e = 0; e < 4; e++) acc[mt][nt][e] = 0.f;

    // prologue: stage 0
#pragma unroll
    for (int i = 0; i < 8; i++) cpasync16(dsts[i], srcs[i]);
    CP_COMMIT();

    for (int c = 0; c < NC1; c++) {
        const int s = c & 1;
        if (c + 1 < NC1) {
            const int k0 = (c + 1) * KC;
            const uint32_t so = (uint32_t)((1 - s) * STAGE_SZ);
#pragma unroll
            for (int i = 0; i < 8; i++) cpasync16(dsts[i] + so, srcs[i] + k0);
            CP_COMMIT();
            CP_WAIT(1);
        } else {
            CP_WAIT(0);
        }
        __syncthreads();
        mma_stage(sb + s * STAGE_SZ, wm, wn, lane, acc);
        __syncthreads();
    }

    // ---- epilogue: stage tables, correction, silu, write act hi/lo ----
    float* sPg = (float*)smem;       // 64 x 8
    float* sPu = sPg + 512;          // 64 x 8
    float* sSf = sPu + 512;          // 128 x 8
    float* sSc = sSf + 1024;         // 128
    if (tid < 128) {
        ((float4*)sPg)[tid] = ((const float4*)(g_Pg + ((size_t)g * IDIM + i0) * GSZ))[tid];
        ((float4*)sPu)[tid] = ((const float4*)(g_Pu + ((size_t)g * IDIM + i0) * GSZ))[tid];
    }
    {
        const int t = tid >> 1, hf = tid & 1;
        ((float4*)sSf)[tid] =
            *(const float4*)(g_soft + ((size_t)(n0 + t) * NGRP + g) * GSZ + hf * 4);
    }
    if (tid < 128) sSc[tid] = g_scalar[(size_t)(n0 + tid) * NGRP + g];
    __syncthreads();

    const int r = lane >> 2, cb = (lane & 3) * 2;
#pragma unroll
    for (int mt = 0; mt < 2; mt++) {
#pragma unroll
        for (int e2 = 0; e2 < 2; e2++) {
            const int trow = wm * 32 + mt * 16 + r + e2 * 8;
            const int n = n0 + trow;
            float sf[8];
#pragma unroll
            for (int s = 0; s < 8; s++) sf[s] = sSf[trow * 8 + s];
            const float scl = sSc[trow];
            __nv_bfloat16* ph = g_acth + ((size_t)g * N_TOK + n) * IDIM + i0;
            __nv_bfloat16* pl = g_actl + ((size_t)g * N_TOK + n) * IDIM + i0;
#pragma unroll
            for (int nt = 0; nt < 4; nt++) {
                __nv_bfloat162 vh, vl;
#pragma unroll
                for (int p = 0; p < 2; p++) {
                    const int icol = wn * 32 + nt * 8 + cb + p;
                    float gv = acc[mt][nt][e2 * 2 + p];
                    float uv = acc[mt][nt + 4][e2 * 2 + p];
#pragma unroll
                    for (int s = 0; s < 8; s++) {
                        gv += sf[s] * sPg[icol * 8 + s];
                        uv += sf[s] * sPu[icol * 8 + s];
                    }
                    const float sig = 1.f / (1.f + expf(-gv));
                    const float a = scl * (gv * sig * uv);
                    const __nv_bfloat16 h = __float2bfloat16(a);
                    const __nv_bfloat16 l = __float2bfloat16(a - __bfloat162float(h));
                    if (p == 0) { vh.x = h; vl.x = l; } else { vh.y = h; vl.y = l; }
                }
                const int icol0 = wn * 32 + nt * 8 + cb;
                *(__nv_bfloat162*)(ph + icol0) = vh;
                *(__nv_bfloat162*)(pl + icol0) = vl;
            }
        }
    }
}

// ---------------------------------------------------------------------------
// G2: y[n0..+128, h0..+128] = sum over (g, k-chunks) act @ Wd^T
// ---------------------------------------------------------------------------
__global__ __launch_bounds__(256, 1) void moe_g2_mma(float* __restrict__ y)
{
    extern __shared__ char smem[];
    const uint32_t sb = s2u(smem);
    const int tid = threadIdx.x, lane = tid & 31;
    const int wm = (tid >> 5) & 3, wn = tid >> 7;
    const int n0 = blockIdx.x * 128, h0 = blockIdx.y * 128;

    // per-thread loader slots: row base (group 0, k 0); per-stage add offsets
    const __nv_bfloat16* srcs[8];
    uint32_t dsts[8];
    int tiles[8];
#pragma unroll
    for (int i = 0; i < 8; i++) {
        const int id = tid + i * 256;
        const int tile = id >> 9, rr = (id >> 2) & 127, cc = id & 3;
        const __nv_bfloat16* p;
        if (tile == 0)      p = g_acth + (size_t)(n0 + rr) * IDIM;
        else if (tile == 1) p = g_actl + (size_t)(n0 + rr) * IDIM;
        else if (tile == 2) p = g_wdh + (size_t)(h0 + rr) * IDIM;
        else                p = g_wdl + (size_t)(h0 + rr) * IDIM;
        srcs[i] = p + cc * 8;
        dsts[i] = sb + tile * TILE_SZ + rr * ROWB + cc * 16;
        tiles[i] = tile;
    }

    float acc[2][8][4];
#pragma unroll
    for (int mt = 0; mt < 2; mt++)
#pragma unroll
        for (int nt = 0; nt < 8; nt++)
#pragma unroll
            for (int e = 0; e < 4; e++) acc[mt][nt][e] = 0.f;

    // prologue: chunk 0 (g=0, k=0)
#pragma unroll
    for (int i = 0; i < 8; i++) cpasync16(dsts[i], srcs[i]);
    CP_COMMIT();

    int gg = 0, kk = 0;  // chunk-index state for the NEXT chunk
    for (int c = 0; c < NC2; c++) {
        const int s = c & 1;
        if (c + 1 < NC2) {
            if (++kk == KCI) { kk = 0; ++gg; }
            const size_t offA = ((size_t)gg * N_TOK) * IDIM + kk * KC;
            const size_t offB = ((size_t)gg * HDIM) * IDIM + kk * KC;
            const uint32_t so = (uint32_t)((1 - s) * STAGE_SZ);
#pragma unroll
            for (int i = 0; i < 8; i++)
                cpasync16(dsts[i] + so, srcs[i] + (tiles[i] < 2 ? offA : offB));
            CP_COMMIT();
            CP_WAIT(1);
        } else {
            CP_WAIT(0);
        }
        __syncthreads();
        mma_stage(sb + s * STAGE_SZ, wm, wn, lane, acc);
        __syncthreads();
    }

    // epilogue: write fp32 y
    const int r = lane >> 2, cb = (lane & 3) * 2;
#pragma unroll
    for (int mt = 0; mt < 2; mt++) {
#pragma unroll
        for (int e2 = 0; e2 < 2; e2++) {
            const int n = n0 + wm * 32 + mt * 16 + r + e2 * 8;
            float* row = y + (size_t)n * HDIM + h0 + wn * 64;
#pragma unroll
            for (int nt = 0; nt < 8; nt++) {
                float2 v;
                v.x = acc[mt][nt][e2 * 2];
                v.y = acc[mt][nt][e2 * 2 + 1];
                *(float2*)(row + nt * 8 + cb) = v;
            }
        }
    }
}

// ---------------------------------------------------------------------------
// Launch
// ---------------------------------------------------------------------------
extern "C" void kernel_launch(void* const* d_in, const int* in_sizes, int n_in,
                              void* d_out, int out_size)
{
    const float* x      = (const float*)d_in[0];
    const float* gate_w = (const float*)d_in[1];
    const float* mask_w = (const float*)d_in[2];
    const float* Wg     = (const float*)d_in[3];
    const float* Wu     = (const float*)d_in[4];
    const float* Wd     = (const float*)d_in[5];
    const void*  invmap = (const void*)d_in[6];
    float* y = (float*)d_out;
    (void)in_sizes; (void)n_in; (void)out_size;

    cudaFuncSetAttribute(moe_g1_mma, cudaFuncAttributeMaxDynamicSharedMemorySize, SMEM_TOTAL);
    cudaFuncSetAttribute(moe_g2_mma, cudaFuncAttributeMaxDynamicSharedMemorySize, SMEM_TOTAL);

    __nv_bfloat16 *xh, *xl, *wgh, *wgl, *wuh, *wul, *wdh, *wdl;
    cudaGetSymbolAddress((void**)&xh,  g_xh);
    cudaGetSymbolAddress((void**)&xl,  g_xl);
    cudaGetSymbolAddress((void**)&wgh, g_wgh);
    cudaGetSymbolAddress((void**)&wgl, g_wgl);
    cudaGetSymbolAddress((void**)&wuh, g_wuh);
    cudaGetSymbolAddress((void**)&wul, g_wul);
    cudaGetSymbolAddress((void**)&wdh, g_wdh);
    cudaGetSymbolAddress((void**)&wdl, g_wdl);

    // prep splits
    split_bf16<<<2048, 256>>>((const float4*)x, (uint2*)xh, (uint2*)xl,
                              (int)((size_t)N_TOK * HDIM / 4));
    split_bf16<<<2048, 256>>>((const float4*)Wg, (uint2*)wgh, (uint2*)wgl,
                              (int)((size_t)NGRP * IDIM * HDIM / 4));
    split_bf16<<<2048, 256>>>((const float4*)Wu, (uint2*)wuh, (uint2*)wul,
                              (int)((size_t)NGRP * IDIM * HDIM / 4));
    split_bf16<<<2048, 256>>>((const float4*)Wd, (uint2*)wdh, (uint2*)wdl,
                              (int)((size_t)NGRP * HDIM * IDIM / 4));

    // routing + rank-8 projections
    moe_route<<<N_TOK, 256>>>(x, gate_w, invmap);
    moe_pproj<<<(NGRP * IDIM) / 8, 256>>>(Wg, Wu, mask_w);

    // G1: gate/up warp-MMA GEMM + fused epilogue
    dim3 g1grid(N_TOK / 128, IDIM / 64, NGRP);
    moe_g1_mma<<<g1grid, 256, SMEM_TOTAL>>>();

    // G2: down-proj accumulated over groups
    dim3 g2grid(N_TOK / 128, HDIM / 128);
    moe_g2_mma<<<g2grid, 256, SMEM_TOTAL>>>(y);
}